// round 8
// baseline (speedup 1.0000x reference)
#include <cuda_runtime.h>
#include <cuda_fp16.h>
#include <math.h>
#include <stdint.h>

#define T_SEQ 2048
#define BATCH 2
#define DMODEL 2048
#define HQ 16
#define HKV 4
#define HD 128
#define M_ROWS (BATCH*T_SEQ)   /* 4096 */
#define DKV (HKV*HD)           /* 512 */
#define FA_SCALE 0.08838834764831845f
#define LOG2E 1.4426950408889634f

// ---------------- scratch ---------------------------------------------------
__device__ __half g_xh[M_ROWS*DMODEL];
__device__ __half g_Wqh[DMODEL*DMODEL];
__device__ __half g_Wkh[DMODEL*DKV];
__device__ __half g_Wvh[DMODEL*DKV];
__device__ __half g_Woh[DMODEL*DMODEL];
__device__ __half g_Qh[M_ROWS*DMODEL];
__device__ __half g_Kh[M_ROWS*DKV];
__device__ __half g_Vh[M_ROWS*DKV];
__device__ __half g_AOh[M_ROWS*DMODEL];
__device__ float  g_cos[T_SEQ*64];
__device__ float  g_sin[T_SEQ*64];

// ---------------- helpers ----------------------------------------------------
__device__ __forceinline__ uint32_t f2h2(float a, float b) {
    __half2 h = __halves2half2(__float2half_rn(a), __float2half_rn(b));
    return *reinterpret_cast<uint32_t*>(&h);
}
__device__ __forceinline__ uint32_t cvta_smem(const void* p) {
    uint32_t a;
    asm("{ .reg .u64 t; cvta.to.shared.u64 t, %1; cvt.u32.u64 %0, t; }"
        : "=r"(a) : "l"(p));
    return a;
}
__device__ __forceinline__ void mma16(float* d, const uint32_t* a, const uint32_t* b) {
    asm volatile("mma.sync.aligned.m16n8k16.row.col.f32.f16.f16.f32 "
        "{%0,%1,%2,%3}, {%4,%5,%6,%7}, {%8,%9}, {%0,%1,%2,%3};"
        : "+f"(d[0]), "+f"(d[1]), "+f"(d[2]), "+f"(d[3])
        : "r"(a[0]), "r"(a[1]), "r"(a[2]), "r"(a[3]), "r"(b[0]), "r"(b[1]));
}
__device__ __forceinline__ void ldsm4(uint32_t* r, uint32_t a) {
    asm volatile("ldmatrix.sync.aligned.m8n8.x4.shared.b16 {%0,%1,%2,%3}, [%4];"
        : "=r"(r[0]), "=r"(r[1]), "=r"(r[2]), "=r"(r[3]) : "r"(a));
}
__device__ __forceinline__ void ldsm4t(uint32_t* r, uint32_t a) {
    asm volatile("ldmatrix.sync.aligned.m8n8.x4.trans.shared.b16 {%0,%1,%2,%3}, [%4];"
        : "=r"(r[0]), "=r"(r[1]), "=r"(r[2]), "=r"(r[3]) : "r"(a));
}
__device__ __forceinline__ void cp16(uint32_t dst, const void* src) {
    asm volatile("cp.async.cg.shared.global [%0], [%1], 16;" :: "r"(dst), "l"(src));
}
#define CPCOMMIT() asm volatile("cp.async.commit_group;" ::: "memory")
#define CPWAIT1()  asm volatile("cp.async.wait_group 1;" ::: "memory")
#define CPWAIT0()  asm volatile("cp.async.wait_group 0;" ::: "memory")

// ---------------- input conversion fp32 -> fp16 ------------------------------
#define N_X  ((long)M_ROWS*DMODEL/4)
#define N_WQ ((long)DMODEL*DMODEL/4)
#define N_WK ((long)DMODEL*DKV/4)
#define CONV_TOTAL (N_X + 2*N_WQ + 2*N_WK)

__global__ void conv_all(const float* __restrict__ x, const float* __restrict__ wq,
                         const float* __restrict__ wk, const float* __restrict__ wv,
                         const float* __restrict__ wo) {
    long i = (long)blockIdx.x*256 + threadIdx.x;
    const float* src; __half* dst; long off;
    if (i < N_X)                       { src = x;  dst = g_xh;  off = i; }
    else if (i < N_X + N_WQ)           { src = wq; dst = g_Wqh; off = i - N_X; }
    else if (i < N_X + N_WQ + N_WK)    { src = wk; dst = g_Wkh; off = i - N_X - N_WQ; }
    else if (i < N_X + N_WQ + 2*N_WK)  { src = wv; dst = g_Wvh; off = i - N_X - N_WQ - N_WK; }
    else if (i < CONV_TOTAL)           { src = wo; dst = g_Woh; off = i - N_X - N_WQ - 2*N_WK; }
    else return;
    float4 v = *(const float4*)(src + off*4);
    uint2 u; u.x = f2h2(v.x, v.y); u.y = f2h2(v.z, v.w);
    *(uint2*)(dst + off*4) = u;
}

// ---------------- RoPE table --------------------------------------------------
__global__ void rope_table_kernel() {
    int idx = blockIdx.x*blockDim.x + threadIdx.x;
    if (idx >= T_SEQ*64) return;
    int t = idx >> 6, i = idx & 63;
    float inv = powf(10000.0f, -(float)i / 64.0f);
    float ang = (float)t * inv;
    g_cos[idx] = (float)cos((double)ang);
    g_sin[idx] = (float)sin((double)ang);
}

// ---------------- fp16 GEMM: cp.async 3-stage + ldmatrix + fused RoPE --------
// C[M,N] = A[M,K](fp16) @ B[K,N](fp16). 128x128 CTA, 8 warps (4x2), BK=64.
// mode 0: fp32 out (O-proj). mode 1: QKV fused — tiles [0,t0) Q (rope, rs_q),
// [t0,t0+t1) K (rope, rs_k), rest V (plain fp16). Column tiles are 1 head wide.
#define GSTB 32768
#define GEMM_SMEM (3*GSTB)
#define EP 132

__global__ __launch_bounds__(256) void hgemm(
    const __half* __restrict__ A,
    const __half* __restrict__ B0, const __half* __restrict__ B1, const __half* __restrict__ B2,
    void* __restrict__ C0, void* __restrict__ C1, void* __restrict__ C2,
    int t0, int t1, int K, int mode, float rs_q, float rs_k)
{
    extern __shared__ char gsm[];
    const uint32_t sb = cvta_smem(gsm);

    const int tx = blockIdx.x;
    const __half* B; void* C; int N, cb;
    if (tx < t0)           { B = B0; C = C0; N = t0*128; cb = tx*128; }
    else if (tx < t0 + t1) { B = B1; C = C1; N = t1*128; cb = (tx - t0)*128; }
    else { B = B2; C = C2; N = ((int)gridDim.x - t0 - t1)*128; cb = (tx - t0 - t1)*128; }

    const int tid = threadIdx.x;
    const int lane = tid & 31, wid = tid >> 5;
    const int gid = lane >> 2, tig = lane & 3;
    const int wm = wid & 3, wn = wid >> 2;
    const int bm = blockIdx.y * 128;
    const int nc = K >> 6;

    const int ar = tid >> 3, ac = tid & 7;
    const int bk = tid >> 4, bc = tid & 15;
    const uint32_t aswz = (uint32_t)(ac ^ (ar & 7)) << 4;
    const uint32_t bswz = (uint32_t)((bc & 8) | ((bc ^ (bk & 7)) & 7)) << 4;

    auto issue = [&](int c) {
        const uint32_t sA = sb + (c % 3)*GSTB;
        const uint32_t sB = sA + 16384;
        const __half* Ag = A + (size_t)(bm + ar)*K + c*64 + ac*8;
        #pragma unroll
        for (int i = 0; i < 4; i++)
            cp16(sA + (uint32_t)(ar + 32*i)*128 + aswz, Ag + (size_t)(32*i)*K);
        const __half* Bg = B + (size_t)(c*64 + bk)*N + cb + bc*8;
        #pragma unroll
        for (int i = 0; i < 4; i++)
            cp16(sB + (uint32_t)(bk + 16*i)*256 + bswz, Bg + (size_t)(16*i)*N);
        CPCOMMIT();
    };

    float acc[2][8][4];
    #pragma unroll
    for (int mt = 0; mt < 2; mt++)
        #pragma unroll
        for (int nt = 0; nt < 8; nt++)
            #pragma unroll
            for (int e = 0; e < 4; e++) acc[mt][nt][e] = 0.f;

    issue(0); issue(1);

    for (int c = 0; c < nc; ++c) {
        if (c + 2 < nc) { CPWAIT1(); } else { CPWAIT0(); }
        __syncthreads();
        if (c + 2 < nc) issue(c + 2);

        const uint32_t sA = sb + (c % 3)*GSTB;
        const uint32_t sB = sA + 16384;

        #pragma unroll
        for (int ks = 0; ks < 4; ++ks) {
            uint32_t af[2][4];
            #pragma unroll
            for (int mt = 0; mt < 2; mt++) {
                int row = wm*32 + mt*16 + (lane & 15);
                int ch = ks*2 + (lane >> 4);
                ldsm4(af[mt], sA + (uint32_t)row*128 + ((uint32_t)(ch ^ (row & 7)) << 4));
            }
            uint32_t bf[8][2];
            #pragma unroll
            for (int nb = 0; nb < 4; nb++) {
                int kr = ks*16 + (lane & 15);
                int ch = wn*8 + nb*2 + (lane >> 4);
                uint32_t q[4];
                ldsm4t(q, sB + (uint32_t)kr*256 +
                          ((uint32_t)((ch & 8) | ((ch ^ (kr & 7)) & 7)) << 4));
                bf[2*nb][0] = q[0]; bf[2*nb][1] = q[1];
                bf[2*nb+1][0] = q[2]; bf[2*nb+1][1] = q[3];
            }
            #pragma unroll
            for (int mt = 0; mt < 2; mt++)
                #pragma unroll
                for (int nt = 0; nt < 8; nt++)
                    mma16(acc[mt][nt], af[mt], bf[nt]);
        }
    }

    const bool rope = (mode == 1) && (tx < t0 + t1);
    if (rope) {
        // stage fp32 tile through smem, rotate pairs (c, c+64), write fp16
        const float rs = (tx < t0) ? rs_q : rs_k;
        float* buf = (float*)gsm;
        __syncthreads();   // all warps done reading stage buffers
        #pragma unroll
        for (int mt = 0; mt < 2; mt++) {
            int r = wm*32 + mt*16 + gid;
            #pragma unroll
            for (int nt = 0; nt < 8; nt++) {
                int c = wn*64 + nt*8 + 2*tig;
                *(float2*)(buf + r*EP + c)       = make_float2(acc[mt][nt][0], acc[mt][nt][1]);
                *(float2*)(buf + (r+8)*EP + c)   = make_float2(acc[mt][nt][2], acc[mt][nt][3]);
            }
        }
        __syncthreads();
        __half* Ch = (__half*)C;
        #pragma unroll
        for (int it = 0; it < 16; ++it) {
            int i = tid + it*256;            // 128 rows x 32 col-pairs
            int r = i >> 5, cp = (i & 31)*2; // cp in [0,64)
            int t = (bm + r) & (T_SEQ - 1);
            float2 a  = *(const float2*)(buf + r*EP + cp);
            float2 bb = *(const float2*)(buf + r*EP + cp + 64);
            float2 co = *(const float2*)(g_cos + t*64 + cp);
            float2 si = *(const float2*)(g_sin + t*64 + cp);
            __half* row = Ch + (size_t)(bm + r)*N + cb;
            *(uint32_t*)(row + cp)      = f2h2((a.x*co.x - bb.x*si.x)*rs, (a.y*co.y - bb.y*si.y)*rs);
            *(uint32_t*)(row + cp + 64) = f2h2((bb.x*co.x + a.x*si.x)*rs, (bb.y*co.y + a.y*si.y)*rs);
        }
    } else if (mode == 1) {
        __half* Ch = (__half*)C;
        #pragma unroll
        for (int mt = 0; mt < 2; mt++) {
            int r0 = bm + wm*32 + mt*16 + gid;
            #pragma unroll
            for (int nt = 0; nt < 8; nt++) {
                int col = cb + wn*64 + nt*8 + 2*tig;
                *(uint32_t*)(Ch + (size_t)r0 * N + col)       = f2h2(acc[mt][nt][0], acc[mt][nt][1]);
                *(uint32_t*)(Ch + (size_t)(r0 + 8) * N + col) = f2h2(acc[mt][nt][2], acc[mt][nt][3]);
            }
        }
    } else {
        float* Cf = (float*)C;
        #pragma unroll
        for (int mt = 0; mt < 2; mt++) {
            int r0 = bm + wm*32 + mt*16 + gid;
            #pragma unroll
            for (int nt = 0; nt < 8; nt++) {
                int col = cb + wn*64 + nt*8 + 2*tig;
                *(float2*)(Cf + (size_t)r0 * N + col)       = make_float2(acc[mt][nt][0], acc[mt][nt][1]);
                *(float2*)(Cf + (size_t)(r0 + 8) * N + col) = make_float2(acc[mt][nt][2], acc[mt][nt][3]);
            }
        }
    }
}

// ---------------- flash attention: Q frags in regs, 3-stage KV ---------------
#define FKVSTB 32768
#define FLASH_SMEM (32768 + 3*FKVSTB)

__global__ __launch_bounds__(256) void flash_h2(
    const __half* __restrict__ Qh, const __half* __restrict__ Kh,
    const __half* __restrict__ Vh, __half* __restrict__ AOh)
{
    extern __shared__ char fsm[];
    const uint32_t sb = cvta_smem(fsm);
    const int tid = threadIdx.x, lane = tid & 31, wid = tid >> 5;
    const int gid = lane >> 2, tig = lane & 3;
    const int qt = 15 - blockIdx.x;
    const int h = blockIdx.y, b = blockIdx.z;
    const int hk = h >> 2;
    const int wrow = wid * 16;
    const int q0 = b*T_SEQ + qt*128;
    const int nkt = 2*qt + 2;

    auto issue_kv = [&](int kt) {
        const uint32_t sK = sb + 32768 + (kt % 3)*FKVSTB;
        const uint32_t sV = sK + 16384;
        const int k0g = b*T_SEQ + kt*64;
        const __half* Kg = Kh + (size_t)k0g*DKV + hk*HD;
        const __half* Vg = Vh + (size_t)k0g*DKV + hk*HD;
        #pragma unroll
        for (int i = 0; i < 4; i++) {
            int id = tid + 256*i;
            int r = id >> 4, c = id & 15;
            uint32_t o = (uint32_t)r*256 + ((uint32_t)((c & 8) | ((c ^ (r & 7)) & 7)) << 4);
            cp16(sK + o, Kg + (size_t)r*DKV + c*8);
            cp16(sV + o, Vg + (size_t)r*DKV + c*8);
        }
        CPCOMMIT();
    };

    {
        const __half* Qg = Qh + (size_t)q0*DMODEL + h*HD;
        #pragma unroll
        for (int i = 0; i < 8; i++) {
            int id = tid + 256*i;
            int r = id >> 4, c = id & 15;
            uint32_t o = (uint32_t)r*256 + ((uint32_t)((c & 8) | ((c ^ (r & 7)) & 7)) << 4);
            cp16(sb + o, Qg + (size_t)r*DMODEL + c*8);
        }
        const __half* Kg = Kh + (size_t)(b*T_SEQ)*DKV + hk*HD;
        const __half* Vg = Vh + (size_t)(b*T_SEQ)*DKV + hk*HD;
        const uint32_t sK = sb + 32768, sV = sK + 16384;
        #pragma unroll
        for (int i = 0; i < 4; i++) {
            int id = tid + 256*i;
            int r = id >> 4, c = id & 15;
            uint32_t o = (uint32_t)r*256 + ((uint32_t)((c & 8) | ((c ^ (r & 7)) & 7)) << 4);
            cp16(sK + o, Kg + (size_t)r*DKV + c*8);
            cp16(sV + o, Vg + (size_t)r*DKV + c*8);
        }
        CPCOMMIT();
        issue_kv(1);
    }

    float oacc[16][4];
    #pragma unroll
    for (int nt = 0; nt < 16; nt++)
        #pragma unroll
        for (int e = 0; e < 4; e++) oacc[nt][e] = 0.f;
    float l0 = 0.f, l1 = 0.f;

    uint32_t qf[8][4];
    bool qloaded = false;

    for (int kt = 0; kt < nkt; ++kt) {
        if (kt + 2 < nkt) { CPWAIT1(); } else { CPWAIT0(); }
        __syncthreads();
        if (kt + 2 < nkt) issue_kv(kt + 2);

        if (!qloaded) {
            #pragma unroll
            for (int ks = 0; ks < 8; ++ks) {
                int row = wrow + (lane & 15);
                int ch = ks*2 + (lane >> 4);
                ldsm4(qf[ks], sb + (uint32_t)row*256 +
                          ((uint32_t)((ch & 8) | ((ch ^ (row & 7)) & 7)) << 4));
            }
            qloaded = true;
        }

        const uint32_t sK = sb + 32768 + (kt % 3)*FKVSTB;
        const uint32_t sV = sK + 16384;

        float sacc[8][4];
        #pragma unroll
        for (int nt = 0; nt < 8; nt++)
            #pragma unroll
            for (int e = 0; e < 4; e++) sacc[nt][e] = 0.f;

        #pragma unroll
        for (int ks = 0; ks < 8; ++ks) {
            #pragma unroll
            for (int np = 0; np < 4; np++) {
                int row = np*16 + (lane & 15);
                int ch = ks*2 + (lane >> 4);
                uint32_t q[4];
                ldsm4(q, sK + (uint32_t)row*256 +
                          ((uint32_t)((ch & 8) | ((ch ^ (row & 7)) & 7)) << 4));
                uint32_t bf0[2] = {q[0], q[2]}, bf1[2] = {q[1], q[3]};
                mma16(sacc[2*np],   qf[ks], bf0);
                mma16(sacc[2*np+1], qf[ks], bf1);
            }
        }

        const int qg0 = qt*128 + wrow + gid;
        const int kb  = kt*64;
        uint32_t pf[4][4];
        #pragma unroll
        for (int k2 = 0; k2 < 4; ++k2) {
            float p[2][4];
            #pragma unroll
            for (int j = 0; j < 2; j++) {
                int nt = 2*k2 + j;
                int c0 = kb + nt*8 + 2*tig;
                p[j][0] = (c0     <= qg0    ) ? exp2f(sacc[nt][0]) : 0.f;
                p[j][1] = (c0 + 1 <= qg0    ) ? exp2f(sacc[nt][1]) : 0.f;
                p[j][2] = (c0     <= qg0 + 8) ? exp2f(sacc[nt][2]) : 0.f;
                p[j][3] = (c0 + 1 <= qg0 + 8) ? exp2f(sacc[nt][3]) : 0.f;
            }
            pf[k2][0] = f2h2(p[0][0], p[0][1]);
            pf[k2][1] = f2h2(p[0][2], p[0][3]);
            pf[k2][2] = f2h2(p[1][0], p[1][1]);
            pf[k2][3] = f2h2(p[1][2], p[1][3]);
            float2 t;
            t = __half22float2(*(__half2*)&pf[k2][0]); l0 += t.x + t.y;
            t = __half22float2(*(__half2*)&pf[k2][2]); l0 += t.x + t.y;
            t = __half22float2(*(__half2*)&pf[k2][1]); l1 += t.x + t.y;
            t = __half22float2(*(__half2*)&pf[k2][3]); l1 += t.x + t.y;
        }

        #pragma unroll
        for (int k2 = 0; k2 < 4; ++k2) {
            #pragma unroll
            for (int nb = 0; nb < 8; nb++) {
                int kr = k2*16 + (lane & 15);
                int ch = nb*2 + (lane >> 4);
                uint32_t q[4];
                ldsm4t(q, sV + (uint32_t)kr*256 +
                          ((uint32_t)((ch & 8) | ((ch ^ (kr & 7)) & 7)) << 4));
                uint32_t bf0[2] = {q[0], q[1]}, bf1[2] = {q[2], q[3]};
                mma16(oacc[2*nb],   pf[k2], bf0);
                mma16(oacc[2*nb+1], pf[k2], bf1);
            }
        }
    }

    l0 += __shfl_xor_sync(0xffffffff, l0, 1);
    l0 += __shfl_xor_sync(0xffffffff, l0, 2);
    l1 += __shfl_xor_sync(0xffffffff, l1, 1);
    l1 += __shfl_xor_sync(0xffffffff, l1, 2);
    const float inv0 = 1.f / l0, inv1 = 1.f / l1;

    const int r0 = q0 + wrow + gid;
    #pragma unroll
    for (int nt = 0; nt < 16; nt++) {
        int col = h*HD + nt*8 + 2*tig;
        *(uint32_t*)(AOh + (size_t)r0 * DMODEL + col) =
            f2h2(oacc[nt][0]*inv0, oacc[nt][1]*inv0);
        *(uint32_t*)(AOh + (size_t)(r0 + 8) * DMODEL + col) =
            f2h2(oacc[nt][2]*inv1, oacc[nt][3]*inv1);
    }
}

// ---------------- launch -----------------------------------------------------
extern "C" void kernel_launch(void* const* d_in, const int* in_sizes, int n_in,
                              void* d_out, int out_size)
{
    const float* x  = (const float*)d_in[0];
    const float* Wq = (const float*)d_in[1];
    const float* Wk = (const float*)d_in[2];
    const float* Wv = (const float*)d_in[3];
    const float* Wo = (const float*)d_in[4];
    float* out = (float*)d_out;

    __half *xh, *Wqh, *Wkh, *Wvh, *Woh, *Qh, *Kh, *Vh, *AOh;
    cudaGetSymbolAddress((void**)&xh,  g_xh);
    cudaGetSymbolAddress((void**)&Wqh, g_Wqh);
    cudaGetSymbolAddress((void**)&Wkh, g_Wkh);
    cudaGetSymbolAddress((void**)&Wvh, g_Wvh);
    cudaGetSymbolAddress((void**)&Woh, g_Woh);
    cudaGetSymbolAddress((void**)&Qh,  g_Qh);
    cudaGetSymbolAddress((void**)&Kh,  g_Kh);
    cudaGetSymbolAddress((void**)&Vh,  g_Vh);
    cudaGetSymbolAddress((void**)&AOh, g_AOh);

    cudaFuncSetAttribute(hgemm,    cudaFuncAttributeMaxDynamicSharedMemorySize, GEMM_SMEM);
    cudaFuncSetAttribute(flash_h2, cudaFuncAttributeMaxDynamicSharedMemorySize, FLASH_SMEM);

    rope_table_kernel<<<(T_SEQ*64 + 255)/256, 256>>>();
    conv_all<<<(int)((CONV_TOTAL + 255)/256), 256>>>(x, Wq, Wk, Wv, Wo);

    // fused QKV projection with fused RoPE epilogue:
    // tiles 0-15 -> Q (rope, scale*log2e), 16-19 -> K (rope), 20-23 -> V (plain)
    hgemm<<<dim3(24, M_ROWS/128), 256, GEMM_SMEM>>>(
        xh, Wqh, Wkh, Wvh, Qh, Kh, Vh, 16, 4, DMODEL, 1, FA_SCALE*LOG2E, 1.0f);

    flash_h2<<<dim3(16, HQ, BATCH), 256, FLASH_SMEM>>>(Qh, Kh, Vh, AOh);

    // output projection (fp32 out)
    hgemm<<<dim3(16, M_ROWS/128), 256, GEMM_SMEM>>>(
        AOh, Woh, Woh, Woh, out, out, out, 16, 0, DMODEL, 0, 0.f, 0.f);
}

// round 9
// speedup vs baseline: 1.1432x; 1.1432x over previous
#include <cuda_runtime.h>
#include <cuda_fp16.h>
#include <math.h>
#include <stdint.h>

#define T_SEQ 2048
#define BATCH 2
#define DMODEL 2048
#define HQ 16
#define HKV 4
#define HD 128
#define M_ROWS (BATCH*T_SEQ)   /* 4096 */
#define DKV (HKV*HD)           /* 512 */
#define FA_SCALE 0.08838834764831845f
#define LOG2E 1.4426950408889634f

// ---------------- scratch ---------------------------------------------------
__device__ __half g_xh[M_ROWS*DMODEL];
__device__ __half g_Wqh[DMODEL*DMODEL];
__device__ __half g_Wkh[DMODEL*DKV];
__device__ __half g_Wvh[DMODEL*DKV];
__device__ __half g_Woh[DMODEL*DMODEL];
__device__ __half g_Qh[M_ROWS*DMODEL];
__device__ __half g_Kh[M_ROWS*DKV];
__device__ __half g_Vh[M_ROWS*DKV];
__device__ __half g_AOh[M_ROWS*DMODEL];
__device__ float  g_cos[T_SEQ*64];
__device__ float  g_sin[T_SEQ*64];

// ---------------- helpers ----------------------------------------------------
__device__ __forceinline__ uint32_t f2h2(float a, float b) {
    __half2 h = __halves2half2(__float2half_rn(a), __float2half_rn(b));
    return *reinterpret_cast<uint32_t*>(&h);
}
__device__ __forceinline__ uint32_t cvta_smem(const void* p) {
    uint32_t a;
    asm("{ .reg .u64 t; cvta.to.shared.u64 t, %1; cvt.u32.u64 %0, t; }"
        : "=r"(a) : "l"(p));
    return a;
}
__device__ __forceinline__ void mma16(float* d, const uint32_t* a, const uint32_t* b) {
    asm volatile("mma.sync.aligned.m16n8k16.row.col.f32.f16.f16.f32 "
        "{%0,%1,%2,%3}, {%4,%5,%6,%7}, {%8,%9}, {%0,%1,%2,%3};"
        : "+f"(d[0]), "+f"(d[1]), "+f"(d[2]), "+f"(d[3])
        : "r"(a[0]), "r"(a[1]), "r"(a[2]), "r"(a[3]), "r"(b[0]), "r"(b[1]));
}
__device__ __forceinline__ void ldsm4(uint32_t* r, uint32_t a) {
    asm volatile("ldmatrix.sync.aligned.m8n8.x4.shared.b16 {%0,%1,%2,%3}, [%4];"
        : "=r"(r[0]), "=r"(r[1]), "=r"(r[2]), "=r"(r[3]) : "r"(a));
}
__device__ __forceinline__ void ldsm4t(uint32_t* r, uint32_t a) {
    asm volatile("ldmatrix.sync.aligned.m8n8.x4.trans.shared.b16 {%0,%1,%2,%3}, [%4];"
        : "=r"(r[0]), "=r"(r[1]), "=r"(r[2]), "=r"(r[3]) : "r"(a));
}
__device__ __forceinline__ void cp16(uint32_t dst, const void* src) {
    asm volatile("cp.async.cg.shared.global [%0], [%1], 16;" :: "r"(dst), "l"(src));
}
#define CPCOMMIT() asm volatile("cp.async.commit_group;" ::: "memory")
#define CPWAIT1()  asm volatile("cp.async.wait_group 1;" ::: "memory")
#define CPWAIT0()  asm volatile("cp.async.wait_group 0;" ::: "memory")

// ---------------- input conversion fp32 -> fp16 ------------------------------
#define N_X  ((long)M_ROWS*DMODEL/4)
#define N_WQ ((long)DMODEL*DMODEL/4)
#define N_WK ((long)DMODEL*DKV/4)
#define CONV_TOTAL (N_X + 2*N_WQ + 2*N_WK)

__global__ void conv_all(const float* __restrict__ x, const float* __restrict__ wq,
                         const float* __restrict__ wk, const float* __restrict__ wv,
                         const float* __restrict__ wo) {
    long i = (long)blockIdx.x*256 + threadIdx.x;
    const float* src; __half* dst; long off;
    if (i < N_X)                       { src = x;  dst = g_xh;  off = i; }
    else if (i < N_X + N_WQ)           { src = wq; dst = g_Wqh; off = i - N_X; }
    else if (i < N_X + N_WQ + N_WK)    { src = wk; dst = g_Wkh; off = i - N_X - N_WQ; }
    else if (i < N_X + N_WQ + 2*N_WK)  { src = wv; dst = g_Wvh; off = i - N_X - N_WQ - N_WK; }
    else if (i < CONV_TOTAL)           { src = wo; dst = g_Woh; off = i - N_X - N_WQ - 2*N_WK; }
    else return;
    float4 v = *(const float4*)(src + off*4);
    uint2 u; u.x = f2h2(v.x, v.y); u.y = f2h2(v.z, v.w);
    *(uint2*)(dst + off*4) = u;
}

// ---------------- RoPE ------------------------------------------------------
__global__ void rope_table_kernel() {
    int idx = blockIdx.x*blockDim.x + threadIdx.x;
    if (idx >= T_SEQ*64) return;
    int t = idx >> 6, i = idx & 63;
    float inv = powf(10000.0f, -(float)i / 64.0f);
    float ang = (float)t * inv;
    g_cos[idx] = (float)cos((double)ang);
    g_sin[idx] = (float)sin((double)ang);
}

// in-place fp16 RoPE (each thread reads+writes only its own two words)
__global__ void rope_h16_kernel(__half* __restrict__ buf, int heads, float scale) {
    int idx = blockIdx.x*blockDim.x + threadIdx.x;
    int total = M_ROWS * heads * 32;
    if (idx >= total) return;
    int i2 = idx & 31;
    int h = (idx >> 5) % heads;
    int m = idx / (32 * heads);
    int t = m & (T_SEQ - 1);
    int d0 = 2*i2;
    uint32_t* p = (uint32_t*)(buf + (size_t)m * heads * HD + h * HD);
    float2 a = __half22float2(*(__half2*)&p[i2]);
    float2 b = __half22float2(*(__half2*)&p[32 + i2]);
    float c0 = g_cos[t*64 + d0], c1 = g_cos[t*64 + d0 + 1];
    float s0 = g_sin[t*64 + d0], s1 = g_sin[t*64 + d0 + 1];
    p[i2]      = f2h2((a.x*c0 - b.x*s0)*scale, (a.y*c1 - b.y*s1)*scale);
    p[32 + i2] = f2h2((b.x*c0 + a.x*s0)*scale, (b.y*c1 + a.y*s1)*scale);
}

// ---------------- fp16 GEMM: cp.async 3-stage + ldmatrix ---------------------
// C[M,N] = A[M,K](fp16) @ B[K,N](fp16). 128x128 CTA, 8 warps (4x2), BK=64.
// half_out: C is __half*, else float*.
#define GSTB 32768
#define GEMM_SMEM (3*GSTB)

__global__ __launch_bounds__(256) void hgemm(
    const __half* __restrict__ A,
    const __half* __restrict__ B0, const __half* __restrict__ B1, const __half* __restrict__ B2,
    void* __restrict__ C0, void* __restrict__ C1, void* __restrict__ C2,
    int t0, int t1, int K, int half_out)
{
    extern __shared__ char gsm[];
    const uint32_t sb = cvta_smem(gsm);

    const int tx = blockIdx.x;
    const __half* B; void* C; int N, cb;
    if (tx < t0)           { B = B0; C = C0; N = t0*128; cb = tx*128; }
    else if (tx < t0 + t1) { B = B1; C = C1; N = t1*128; cb = (tx - t0)*128; }
    else { B = B2; C = C2; N = ((int)gridDim.x - t0 - t1)*128; cb = (tx - t0 - t1)*128; }

    const int tid = threadIdx.x;
    const int lane = tid & 31, wid = tid >> 5;
    const int gid = lane >> 2, tig = lane & 3;
    const int wm = wid & 3, wn = wid >> 2;
    const int bm = blockIdx.y * 128;
    const int nc = K >> 6;

    const int ar = tid >> 3, ac = tid & 7;
    const int bk = tid >> 4, bc = tid & 15;
    const uint32_t aswz = (uint32_t)(ac ^ (ar & 7)) << 4;
    const uint32_t bswz = (uint32_t)((bc & 8) | ((bc ^ (bk & 7)) & 7)) << 4;

    auto issue = [&](int c) {
        const uint32_t sA = sb + (c % 3)*GSTB;
        const uint32_t sB = sA + 16384;
        const __half* Ag = A + (size_t)(bm + ar)*K + c*64 + ac*8;
        #pragma unroll
        for (int i = 0; i < 4; i++)
            cp16(sA + (uint32_t)(ar + 32*i)*128 + aswz, Ag + (size_t)(32*i)*K);
        const __half* Bg = B + (size_t)(c*64 + bk)*N + cb + bc*8;
        #pragma unroll
        for (int i = 0; i < 4; i++)
            cp16(sB + (uint32_t)(bk + 16*i)*256 + bswz, Bg + (size_t)(16*i)*N);
        CPCOMMIT();
    };

    float acc[2][8][4];
    #pragma unroll
    for (int mt = 0; mt < 2; mt++)
        #pragma unroll
        for (int nt = 0; nt < 8; nt++)
            #pragma unroll
            for (int e = 0; e < 4; e++) acc[mt][nt][e] = 0.f;

    issue(0); issue(1);

    for (int c = 0; c < nc; ++c) {
        if (c + 2 < nc) { CPWAIT1(); } else { CPWAIT0(); }
        __syncthreads();
        if (c + 2 < nc) issue(c + 2);

        const uint32_t sA = sb + (c % 3)*GSTB;
        const uint32_t sB = sA + 16384;

        #pragma unroll
        for (int ks = 0; ks < 4; ++ks) {
            uint32_t af[2][4];
            #pragma unroll
            for (int mt = 0; mt < 2; mt++) {
                int row = wm*32 + mt*16 + (lane & 15);
                int ch = ks*2 + (lane >> 4);
                ldsm4(af[mt], sA + (uint32_t)row*128 + ((uint32_t)(ch ^ (row & 7)) << 4));
            }
            uint32_t bf[8][2];
            #pragma unroll
            for (int nb = 0; nb < 4; nb++) {
                int kr = ks*16 + (lane & 15);
                int ch = wn*8 + nb*2 + (lane >> 4);
                uint32_t q[4];
                ldsm4t(q, sB + (uint32_t)kr*256 +
                          ((uint32_t)((ch & 8) | ((ch ^ (kr & 7)) & 7)) << 4));
                bf[2*nb][0] = q[0]; bf[2*nb][1] = q[1];
                bf[2*nb+1][0] = q[2]; bf[2*nb+1][1] = q[3];
            }
            #pragma unroll
            for (int mt = 0; mt < 2; mt++)
                #pragma unroll
                for (int nt = 0; nt < 8; nt++)
                    mma16(acc[mt][nt], af[mt], bf[nt]);
        }
    }

    if (half_out) {
        __half* Ch = (__half*)C;
        #pragma unroll
        for (int mt = 0; mt < 2; mt++) {
            int r0 = bm + wm*32 + mt*16 + gid;
            #pragma unroll
            for (int nt = 0; nt < 8; nt++) {
                int col = cb + wn*64 + nt*8 + 2*tig;
                *(uint32_t*)(Ch + (size_t)r0 * N + col)       = f2h2(acc[mt][nt][0], acc[mt][nt][1]);
                *(uint32_t*)(Ch + (size_t)(r0 + 8) * N + col) = f2h2(acc[mt][nt][2], acc[mt][nt][3]);
            }
        }
    } else {
        float* Cf = (float*)C;
        #pragma unroll
        for (int mt = 0; mt < 2; mt++) {
            int r0 = bm + wm*32 + mt*16 + gid;
            #pragma unroll
            for (int nt = 0; nt < 8; nt++) {
                int col = cb + wn*64 + nt*8 + 2*tig;
                *(float2*)(Cf + (size_t)r0 * N + col)       = make_float2(acc[mt][nt][0], acc[mt][nt][1]);
                *(float2*)(Cf + (size_t)(r0 + 8) * N + col) = make_float2(acc[mt][nt][2], acc[mt][nt][3]);
            }
        }
    }
}

// ---------------- flash attention: BQ=64, 4 warps, 2 CTAs/SM ----------------
// 128 threads, warp = 16 q-rows. SMEM: Q 16KB + 3 stages x (K16 + V16) = 112KB.
#define FKVSTB 32768
#define FQSZ   16384
#define FLASH_SMEM (FQSZ + 3*FKVSTB)

__global__ __launch_bounds__(128) void flash_h2(
    const __half* __restrict__ Qh, const __half* __restrict__ Kh,
    const __half* __restrict__ Vh, __half* __restrict__ AOh)
{
    extern __shared__ char fsm[];
    const uint32_t sb = cvta_smem(fsm);
    const int tid = threadIdx.x, lane = tid & 31, wid = tid >> 5;
    const int gid = lane >> 2, tig = lane & 3;
    const int qt = 31 - blockIdx.x;          // big tiles first
    const int h = blockIdx.y, b = blockIdx.z;
    const int hk = h >> 2;
    const int wrow = wid * 16;
    const int q0 = b*T_SEQ + qt*64;
    const int nkt = qt + 1;

    auto issue_kv = [&](int kt) {
        const uint32_t sK = sb + FQSZ + (kt % 3)*FKVSTB;
        const uint32_t sV = sK + 16384;
        const int k0g = b*T_SEQ + kt*64;
        const __half* Kg = Kh + (size_t)k0g*DKV + hk*HD;
        const __half* Vg = Vh + (size_t)k0g*DKV + hk*HD;
        #pragma unroll
        for (int i = 0; i < 8; i++) {
            int id = tid + 128*i;
            int r = id >> 4, c = id & 15;
            uint32_t o = (uint32_t)r*256 + ((uint32_t)((c & 8) | ((c ^ (r & 7)) & 7)) << 4);
            cp16(sK + o, Kg + (size_t)r*DKV + c*8);
            cp16(sV + o, Vg + (size_t)r*DKV + c*8);
        }
        CPCOMMIT();
    };

    // group 0: Q tile + KV(0); group 1: KV(1)
    {
        const __half* Qg = Qh + (size_t)q0*DMODEL + h*HD;
        #pragma unroll
        for (int i = 0; i < 8; i++) {
            int id = tid + 128*i;
            int r = id >> 4, c = id & 15;
            uint32_t o = (uint32_t)r*256 + ((uint32_t)((c & 8) | ((c ^ (r & 7)) & 7)) << 4);
            cp16(sb + o, Qg + (size_t)r*DMODEL + c*8);
        }
        const __half* Kg = Kh + (size_t)(b*T_SEQ)*DKV + hk*HD;
        const __half* Vg = Vh + (size_t)(b*T_SEQ)*DKV + hk*HD;
        const uint32_t sK = sb + FQSZ, sV = sK + 16384;
        #pragma unroll
        for (int i = 0; i < 8; i++) {
            int id = tid + 128*i;
            int r = id >> 4, c = id & 15;
            uint32_t o = (uint32_t)r*256 + ((uint32_t)((c & 8) | ((c ^ (r & 7)) & 7)) << 4);
            cp16(sK + o, Kg + (size_t)r*DKV + c*8);
            cp16(sV + o, Vg + (size_t)r*DKV + c*8);
        }
        CPCOMMIT();
        issue_kv(1);      // harmless OOB-free prefetch even when nkt==1 (rows < T_SEQ)
    }

    float oacc[16][4];
    #pragma unroll
    for (int nt = 0; nt < 16; nt++)
        #pragma unroll
        for (int e = 0; e < 4; e++) oacc[nt][e] = 0.f;
    float l0 = 0.f, l1 = 0.f;

    uint32_t qf[8][4];
    bool qloaded = false;

    for (int kt = 0; kt < nkt; ++kt) {
        if (kt + 2 < nkt) { CPWAIT1(); } else { CPWAIT0(); }
        __syncthreads();
        if (kt + 2 < nkt) issue_kv(kt + 2);

        if (!qloaded) {
            #pragma unroll
            for (int ks = 0; ks < 8; ++ks) {
                int row = wrow + (lane & 15);
                int ch = ks*2 + (lane >> 4);
                ldsm4(qf[ks], sb + (uint32_t)row*256 +
                          ((uint32_t)((ch & 8) | ((ch ^ (row & 7)) & 7)) << 4));
            }
            qloaded = true;
        }

        const uint32_t sK = sb + FQSZ + (kt % 3)*FKVSTB;
        const uint32_t sV = sK + 16384;

        // S = Q @ K^T : warp 16x64, k=128
        float sacc[8][4];
        #pragma unroll
        for (int nt = 0; nt < 8; nt++)
            #pragma unroll
            for (int e = 0; e < 4; e++) sacc[nt][e] = 0.f;

        #pragma unroll
        for (int ks = 0; ks < 8; ++ks) {
            #pragma unroll
            for (int np = 0; np < 4; np++) {
                int row = np*16 + (lane & 15);
                int ch = ks*2 + (lane >> 4);
                uint32_t q[4];
                ldsm4(q, sK + (uint32_t)row*256 +
                          ((uint32_t)((ch & 8) | ((ch ^ (row & 7)) & 7)) << 4));
                uint32_t bf0[2] = {q[0], q[2]}, bf1[2] = {q[1], q[3]};
                mma16(sacc[2*np],   qf[ks], bf0);
                mma16(sacc[2*np+1], qf[ks], bf1);
            }
        }

        // mask + exp2 + pack P into A-fragments
        const int qg0 = qt*64 + wrow + gid;
        const int kb  = kt*64;
        uint32_t pf[4][4];
        #pragma unroll
        for (int k2 = 0; k2 < 4; ++k2) {
            float p[2][4];
            #pragma unroll
            for (int j = 0; j < 2; j++) {
                int nt = 2*k2 + j;
                int c0 = kb + nt*8 + 2*tig;
                p[j][0] = (c0     <= qg0    ) ? exp2f(sacc[nt][0]) : 0.f;
                p[j][1] = (c0 + 1 <= qg0    ) ? exp2f(sacc[nt][1]) : 0.f;
                p[j][2] = (c0     <= qg0 + 8) ? exp2f(sacc[nt][2]) : 0.f;
                p[j][3] = (c0 + 1 <= qg0 + 8) ? exp2f(sacc[nt][3]) : 0.f;
            }
            pf[k2][0] = f2h2(p[0][0], p[0][1]);
            pf[k2][1] = f2h2(p[0][2], p[0][3]);
            pf[k2][2] = f2h2(p[1][0], p[1][1]);
            pf[k2][3] = f2h2(p[1][2], p[1][3]);
            float2 t;
            t = __half22float2(*(__half2*)&pf[k2][0]); l0 += t.x + t.y;
            t = __half22float2(*(__half2*)&pf[k2][2]); l0 += t.x + t.y;
            t = __half22float2(*(__half2*)&pf[k2][1]); l1 += t.x + t.y;
            t = __half22float2(*(__half2*)&pf[k2][3]); l1 += t.x + t.y;
        }

        // O += P @ V : warp 16x128, k=64
        #pragma unroll
        for (int k2 = 0; k2 < 4; ++k2) {
            #pragma unroll
            for (int nb = 0; nb < 8; nb++) {
                int kr = k2*16 + (lane & 15);
                int ch = nb*2 + (lane >> 4);
                uint32_t q[4];
                ldsm4t(q, sV + (uint32_t)kr*256 +
                          ((uint32_t)((ch & 8) | ((ch ^ (kr & 7)) & 7)) << 4));
                uint32_t bf0[2] = {q[0], q[1]}, bf1[2] = {q[2], q[3]};
                mma16(oacc[2*nb],   pf[k2], bf0);
                mma16(oacc[2*nb+1], pf[k2], bf1);
            }
        }
    }

    l0 += __shfl_xor_sync(0xffffffff, l0, 1);
    l0 += __shfl_xor_sync(0xffffffff, l0, 2);
    l1 += __shfl_xor_sync(0xffffffff, l1, 1);
    l1 += __shfl_xor_sync(0xffffffff, l1, 2);
    const float inv0 = 1.f / l0, inv1 = 1.f / l1;

    const int r0 = q0 + wrow + gid;
    #pragma unroll
    for (int nt = 0; nt < 16; nt++) {
        int col = h*HD + nt*8 + 2*tig;
        *(uint32_t*)(AOh + (size_t)r0 * DMODEL + col) =
            f2h2(oacc[nt][0]*inv0, oacc[nt][1]*inv0);
        *(uint32_t*)(AOh + (size_t)(r0 + 8) * DMODEL + col) =
            f2h2(oacc[nt][2]*inv1, oacc[nt][3]*inv1);
    }
}

// ---------------- launch -----------------------------------------------------
extern "C" void kernel_launch(void* const* d_in, const int* in_sizes, int n_in,
                              void* d_out, int out_size)
{
    const float* x  = (const float*)d_in[0];
    const float* Wq = (const float*)d_in[1];
    const float* Wk = (const float*)d_in[2];
    const float* Wv = (const float*)d_in[3];
    const float* Wo = (const float*)d_in[4];
    float* out = (float*)d_out;

    __half *xh, *Wqh, *Wkh, *Wvh, *Woh, *Qh, *Kh, *Vh, *AOh;
    cudaGetSymbolAddress((void**)&xh,  g_xh);
    cudaGetSymbolAddress((void**)&Wqh, g_Wqh);
    cudaGetSymbolAddress((void**)&Wkh, g_Wkh);
    cudaGetSymbolAddress((void**)&Wvh, g_Wvh);
    cudaGetSymbolAddress((void**)&Woh, g_Woh);
    cudaGetSymbolAddress((void**)&Qh,  g_Qh);
    cudaGetSymbolAddress((void**)&Kh,  g_Kh);
    cudaGetSymbolAddress((void**)&Vh,  g_Vh);
    cudaGetSymbolAddress((void**)&AOh, g_AOh);

    cudaFuncSetAttribute(hgemm,    cudaFuncAttributeMaxDynamicSharedMemorySize, GEMM_SMEM);
    cudaFuncSetAttribute(flash_h2, cudaFuncAttributeMaxDynamicSharedMemorySize, FLASH_SMEM);

    rope_table_kernel<<<(T_SEQ*64 + 255)/256, 256>>>();
    conv_all<<<(int)((CONV_TOTAL + 255)/256), 256>>>(x, Wq, Wk, Wv, Wo);

    // fused QKV projection (fp16 out): tiles 0-15 -> Q, 16-19 -> K, 20-23 -> V
    hgemm<<<dim3(24, M_ROWS/128), 256, GEMM_SMEM>>>(
        xh, Wqh, Wkh, Wvh, Qh, Kh, Vh, 16, 4, DMODEL, 1);

    // in-place RoPE; Q pre-scaled by FA_SCALE*log2(e) so flash uses exp2
    rope_h16_kernel<<<(M_ROWS*HQ*32  + 255)/256, 256>>>(Qh, HQ, FA_SCALE*LOG2E);
    rope_h16_kernel<<<(M_ROWS*HKV*32 + 255)/256, 256>>>(Kh, HKV, 1.0f);

    flash_h2<<<dim3(32, HQ, BATCH), 128, FLASH_SMEM>>>(Qh, Kh, Vh, AOh);

    // output projection (fp32 out)
    hgemm<<<dim3(16, M_ROWS/128), 256, GEMM_SMEM>>>(
        AOh, Woh, Woh, Woh, out, out, out, 16, 0, DMODEL, 0);
}

// round 10
// speedup vs baseline: 1.1929x; 1.0435x over previous
#include <cuda_runtime.h>
#include <cuda_fp16.h>
#include <math.h>
#include <stdint.h>

#define T_SEQ 2048
#define BATCH 2
#define DMODEL 2048
#define HQ 16
#define HKV 4
#define HD 128
#define M_ROWS (BATCH*T_SEQ)   /* 4096 */
#define DKV (HKV*HD)           /* 512 */
#define FA_SCALE 0.08838834764831845f
#define LOG2E 1.4426950408889634f

// ---------------- scratch ---------------------------------------------------
__device__ __half g_xh[M_ROWS*DMODEL];
__device__ __half g_Wqh[DMODEL*DMODEL];
__device__ __half g_Wkh[DMODEL*DKV];
__device__ __half g_Wvh[DMODEL*DKV];
__device__ __half g_Woh[DMODEL*DMODEL];
__device__ __half g_Qh[M_ROWS*DMODEL];
__device__ __half g_Kh[M_ROWS*DKV];
__device__ __half g_Vh[M_ROWS*DKV];
__device__ __half g_AOh[M_ROWS*DMODEL];
__device__ float  g_cos[T_SEQ*64];
__device__ float  g_sin[T_SEQ*64];

// ---------------- helpers ----------------------------------------------------
__device__ __forceinline__ uint32_t f2h2(float a, float b) {
    __half2 h = __halves2half2(__float2half_rn(a), __float2half_rn(b));
    return *reinterpret_cast<uint32_t*>(&h);
}
__device__ __forceinline__ uint32_t cvta_smem(const void* p) {
    uint32_t a;
    asm("{ .reg .u64 t; cvta.to.shared.u64 t, %1; cvt.u32.u64 %0, t; }"
        : "=r"(a) : "l"(p));
    return a;
}
__device__ __forceinline__ void mma16(float* d, const uint32_t* a, const uint32_t* b) {
    asm volatile("mma.sync.aligned.m16n8k16.row.col.f32.f16.f16.f32 "
        "{%0,%1,%2,%3}, {%4,%5,%6,%7}, {%8,%9}, {%0,%1,%2,%3};"
        : "+f"(d[0]), "+f"(d[1]), "+f"(d[2]), "+f"(d[3])
        : "r"(a[0]), "r"(a[1]), "r"(a[2]), "r"(a[3]), "r"(b[0]), "r"(b[1]));
}
__device__ __forceinline__ void ldsm4(uint32_t* r, uint32_t a) {
    asm volatile("ldmatrix.sync.aligned.m8n8.x4.shared.b16 {%0,%1,%2,%3}, [%4];"
        : "=r"(r[0]), "=r"(r[1]), "=r"(r[2]), "=r"(r[3]) : "r"(a));
}
__device__ __forceinline__ void ldsm4t(uint32_t* r, uint32_t a) {
    asm volatile("ldmatrix.sync.aligned.m8n8.x4.trans.shared.b16 {%0,%1,%2,%3}, [%4];"
        : "=r"(r[0]), "=r"(r[1]), "=r"(r[2]), "=r"(r[3]) : "r"(a));
}
__device__ __forceinline__ void cp16(uint32_t dst, const void* src) {
    asm volatile("cp.async.cg.shared.global [%0], [%1], 16;" :: "r"(dst), "l"(src));
}
#define CPCOMMIT() asm volatile("cp.async.commit_group;" ::: "memory")
#define CPWAIT1()  asm volatile("cp.async.wait_group 1;" ::: "memory")
#define CPWAIT0()  asm volatile("cp.async.wait_group 0;" ::: "memory")

// ---------------- input conversion fp32 -> fp16 (4 float4 per thread) -------
#define N_X  ((long)M_ROWS*DMODEL/4)
#define N_WQ ((long)DMODEL*DMODEL/4)
#define N_WK ((long)DMODEL*DKV/4)
#define CONV_TOTAL (N_X + 2*N_WQ + 2*N_WK)

__global__ void conv_all(const float* __restrict__ x, const float* __restrict__ wq,
                         const float* __restrict__ wk, const float* __restrict__ wv,
                         const float* __restrict__ wo) {
    long base = (long)blockIdx.x*1024 + threadIdx.x;
    #pragma unroll
    for (int u = 0; u < 4; u++) {
        long i = base + u*256;
        const float* src; __half* dst; long off;
        if (i < N_X)                       { src = x;  dst = g_xh;  off = i; }
        else if (i < N_X + N_WQ)           { src = wq; dst = g_Wqh; off = i - N_X; }
        else if (i < N_X + N_WQ + N_WK)    { src = wk; dst = g_Wkh; off = i - N_X - N_WQ; }
        else if (i < N_X + N_WQ + 2*N_WK)  { src = wv; dst = g_Wvh; off = i - N_X - N_WQ - N_WK; }
        else if (i < CONV_TOTAL)           { src = wo; dst = g_Woh; off = i - N_X - N_WQ - 2*N_WK; }
        else continue;
        float4 v = *(const float4*)(src + off*4);
        uint2 uu; uu.x = f2h2(v.x, v.y); uu.y = f2h2(v.z, v.w);
        *(uint2*)(dst + off*4) = uu;
    }
}

// ---------------- RoPE ------------------------------------------------------
__global__ void rope_table_kernel() {
    int idx = blockIdx.x*blockDim.x + threadIdx.x;
    if (idx >= T_SEQ*64) return;
    int t = idx >> 6, i = idx & 63;
    float inv = powf(10000.0f, -(float)i / 64.0f);
    float ang = (float)t * inv;
    g_cos[idx] = (float)cos((double)ang);
    g_sin[idx] = (float)sin((double)ang);
}

// in-place fp16 RoPE on BOTH Q and K in one launch
#define NQ_ROPE (M_ROWS*HQ*32)
#define NK_ROPE (M_ROWS*HKV*32)
__global__ void rope_qk_kernel(__half* __restrict__ Qh, __half* __restrict__ Kh,
                               float qscale) {
    int idx = blockIdx.x*blockDim.x + threadIdx.x;
    __half* buf; int heads; float scale;
    if (idx < NQ_ROPE)                  { buf = Qh; heads = HQ;  scale = qscale; }
    else if (idx < NQ_ROPE + NK_ROPE)   { buf = Kh; heads = HKV; scale = 1.0f; idx -= NQ_ROPE; }
    else return;
    int i2 = idx & 31;
    int h = (idx >> 5) % heads;
    int m = idx / (32 * heads);
    int t = m & (T_SEQ - 1);
    int d0 = 2*i2;
    uint32_t* p = (uint32_t*)(buf + (size_t)m * heads * HD + h * HD);
    float2 a = __half22float2(*(__half2*)&p[i2]);
    float2 b = __half22float2(*(__half2*)&p[32 + i2]);
    float c0 = g_cos[t*64 + d0], c1 = g_cos[t*64 + d0 + 1];
    float s0 = g_sin[t*64 + d0], s1 = g_sin[t*64 + d0 + 1];
    p[i2]      = f2h2((a.x*c0 - b.x*s0)*scale, (a.y*c1 - b.y*s1)*scale);
    p[32 + i2] = f2h2((b.x*c0 + a.x*s0)*scale, (b.y*c1 + a.y*s1)*scale);
}

// ---------------- fp16 GEMM: cp.async 3-stage + ldmatrix ---------------------
#define GSTB 32768
#define GEMM_SMEM (3*GSTB)

__global__ __launch_bounds__(256) void hgemm(
    const __half* __restrict__ A,
    const __half* __restrict__ B0, const __half* __restrict__ B1, const __half* __restrict__ B2,
    void* __restrict__ C0, void* __restrict__ C1, void* __restrict__ C2,
    int t0, int t1, int K, int half_out)
{
    extern __shared__ char gsm[];
    const uint32_t sb = cvta_smem(gsm);

    const int tx = blockIdx.x;
    const __half* B; void* C; int N, cb;
    if (tx < t0)           { B = B0; C = C0; N = t0*128; cb = tx*128; }
    else if (tx < t0 + t1) { B = B1; C = C1; N = t1*128; cb = (tx - t0)*128; }
    else { B = B2; C = C2; N = ((int)gridDim.x - t0 - t1)*128; cb = (tx - t0 - t1)*128; }

    const int tid = threadIdx.x;
    const int lane = tid & 31, wid = tid >> 5;
    const int gid = lane >> 2, tig = lane & 3;
    const int wm = wid & 3, wn = wid >> 2;
    const int bm = blockIdx.y * 128;
    const int nc = K >> 6;

    const int ar = tid >> 3, ac = tid & 7;
    const int bk = tid >> 4, bc = tid & 15;
    const uint32_t aswz = (uint32_t)(ac ^ (ar & 7)) << 4;
    const uint32_t bswz = (uint32_t)((bc & 8) | ((bc ^ (bk & 7)) & 7)) << 4;

    auto issue = [&](int c) {
        const uint32_t sA = sb + (c % 3)*GSTB;
        const uint32_t sB = sA + 16384;
        const __half* Ag = A + (size_t)(bm + ar)*K + c*64 + ac*8;
        #pragma unroll
        for (int i = 0; i < 4; i++)
            cp16(sA + (uint32_t)(ar + 32*i)*128 + aswz, Ag + (size_t)(32*i)*K);
        const __half* Bg = B + (size_t)(c*64 + bk)*N + cb + bc*8;
        #pragma unroll
        for (int i = 0; i < 4; i++)
            cp16(sB + (uint32_t)(bk + 16*i)*256 + bswz, Bg + (size_t)(16*i)*N);
        CPCOMMIT();
    };

    float acc[2][8][4];
    #pragma unroll
    for (int mt = 0; mt < 2; mt++)
        #pragma unroll
        for (int nt = 0; nt < 8; nt++)
            #pragma unroll
            for (int e = 0; e < 4; e++) acc[mt][nt][e] = 0.f;

    issue(0); issue(1);

    for (int c = 0; c < nc; ++c) {
        if (c + 2 < nc) { CPWAIT1(); } else { CPWAIT0(); }
        __syncthreads();
        if (c + 2 < nc) issue(c + 2);

        const uint32_t sA = sb + (c % 3)*GSTB;
        const uint32_t sB = sA + 16384;

        #pragma unroll
        for (int ks = 0; ks < 4; ++ks) {
            uint32_t af[2][4];
            #pragma unroll
            for (int mt = 0; mt < 2; mt++) {
                int row = wm*32 + mt*16 + (lane & 15);
                int ch = ks*2 + (lane >> 4);
                ldsm4(af[mt], sA + (uint32_t)row*128 + ((uint32_t)(ch ^ (row & 7)) << 4));
            }
            uint32_t bf[8][2];
            #pragma unroll
            for (int nb = 0; nb < 4; nb++) {
                int kr = ks*16 + (lane & 15);
                int ch = wn*8 + nb*2 + (lane >> 4);
                uint32_t q[4];
                ldsm4t(q, sB + (uint32_t)kr*256 +
                          ((uint32_t)((ch & 8) | ((ch ^ (kr & 7)) & 7)) << 4));
                bf[2*nb][0] = q[0]; bf[2*nb][1] = q[1];
                bf[2*nb+1][0] = q[2]; bf[2*nb+1][1] = q[3];
            }
            #pragma unroll
            for (int mt = 0; mt < 2; mt++)
                #pragma unroll
                for (int nt = 0; nt < 8; nt++)
                    mma16(acc[mt][nt], af[mt], bf[nt]);
        }
    }

    if (half_out) {
        __half* Ch = (__half*)C;
        #pragma unroll
        for (int mt = 0; mt < 2; mt++) {
            int r0 = bm + wm*32 + mt*16 + gid;
            #pragma unroll
            for (int nt = 0; nt < 8; nt++) {
                int col = cb + wn*64 + nt*8 + 2*tig;
                *(uint32_t*)(Ch + (size_t)r0 * N + col)       = f2h2(acc[mt][nt][0], acc[mt][nt][1]);
                *(uint32_t*)(Ch + (size_t)(r0 + 8) * N + col) = f2h2(acc[mt][nt][2], acc[mt][nt][3]);
            }
        }
    } else {
        float* Cf = (float*)C;
        #pragma unroll
        for (int mt = 0; mt < 2; mt++) {
            int r0 = bm + wm*32 + mt*16 + gid;
            #pragma unroll
            for (int nt = 0; nt < 8; nt++) {
                int col = cb + wn*64 + nt*8 + 2*tig;
                *(float2*)(Cf + (size_t)r0 * N + col)       = make_float2(acc[mt][nt][0], acc[mt][nt][1]);
                *(float2*)(Cf + (size_t)(r0 + 8) * N + col) = make_float2(acc[mt][nt][2], acc[mt][nt][3]);
            }
        }
    }
}

// ---------------- flash attention: BQ=64, 4 warps, 2 CTAs/SM ----------------
// 128 threads, warp = 16 q-rows. SMEM: Q 16KB + 3 stages x (K16 + V16) = 112KB.
#define FKVSTB 32768
#define FQSZ   16384
#define FLASH_SMEM (FQSZ + 3*FKVSTB)

__global__ __launch_bounds__(128) void flash_h2(
    const __half* __restrict__ Qh, const __half* __restrict__ Kh,
    const __half* __restrict__ Vh, __half* __restrict__ AOh)
{
    extern __shared__ char fsm[];
    const uint32_t sb = cvta_smem(fsm);
    const int tid = threadIdx.x, lane = tid & 31, wid = tid >> 5;
    const int gid = lane >> 2, tig = lane & 3;
    const int qt = 31 - blockIdx.x;          // big tiles first
    const int h = blockIdx.y, b = blockIdx.z;
    const int hk = h >> 2;
    const int wrow = wid * 16;
    const int q0 = b*T_SEQ + qt*64;
    const int nkt = qt + 1;

    // per-thread cp.async offsets (constant across ktiles)
    uint32_t kvo[8]; uint32_t go[8];
    #pragma unroll
    for (int i = 0; i < 8; i++) {
        int id = tid + 128*i;
        int r = id >> 4, c = id & 15;
        kvo[i] = (uint32_t)r*256 + ((uint32_t)((c & 8) | ((c ^ (r & 7)) & 7)) << 4);
        go[i]  = (uint32_t)(r*DKV + c*8);
    }

    const __half* Kbase = Kh + (size_t)(b*T_SEQ)*DKV + hk*HD;
    const __half* Vbase = Vh + (size_t)(b*T_SEQ)*DKV + hk*HD;

    auto issue_kv = [&](int kt) {
        const uint32_t sK = sb + FQSZ + (kt % 3)*FKVSTB;
        const uint32_t sV = sK + 16384;
        const __half* Kg = Kbase + (size_t)(kt*64)*DKV;
        const __half* Vg = Vbase + (size_t)(kt*64)*DKV;
        #pragma unroll
        for (int i = 0; i < 8; i++) {
            cp16(sK + kvo[i], Kg + go[i]);
            cp16(sV + kvo[i], Vg + go[i]);
        }
        CPCOMMIT();
    };

    // group 0: Q tile + KV(0); group 1: KV(1)
    {
        const __half* Qg = Qh + (size_t)q0*DMODEL + h*HD;
        #pragma unroll
        for (int i = 0; i < 8; i++) {
            int id = tid + 128*i;
            int r = id >> 4;
            cp16(sb + kvo[i], Qg + (size_t)r*DMODEL + (id & 15)*8);
        }
        const uint32_t sK = sb + FQSZ, sV = sK + 16384;
        #pragma unroll
        for (int i = 0; i < 8; i++) {
            cp16(sK + kvo[i], Kbase + go[i]);
            cp16(sV + kvo[i], Vbase + go[i]);
        }
        CPCOMMIT();
        issue_kv(1);      // harmless prefetch even when nkt==1 (rows < T_SEQ)
    }

    float oacc[16][4];
    #pragma unroll
    for (int nt = 0; nt < 16; nt++)
        #pragma unroll
        for (int e = 0; e < 4; e++) oacc[nt][e] = 0.f;
    float l0 = 0.f, l1 = 0.f;

    uint32_t qf[8][4];
    bool qloaded = false;

    for (int kt = 0; kt < nkt; ++kt) {
        if (kt + 2 < nkt) { CPWAIT1(); } else { CPWAIT0(); }
        __syncthreads();
        if (kt + 2 < nkt) issue_kv(kt + 2);

        if (!qloaded) {
            #pragma unroll
            for (int ks = 0; ks < 8; ++ks) {
                int row = wrow + (lane & 15);
                int ch = ks*2 + (lane >> 4);
                ldsm4(qf[ks], sb + (uint32_t)row*256 +
                          ((uint32_t)((ch & 8) | ((ch ^ (row & 7)) & 7)) << 4));
            }
            qloaded = true;
        }

        const uint32_t sK = sb + FQSZ + (kt % 3)*FKVSTB;
        const uint32_t sV = sK + 16384;

        // S = Q @ K^T : warp 16x64, k=128
        float sacc[8][4];
        #pragma unroll
        for (int nt = 0; nt < 8; nt++)
            #pragma unroll
            for (int e = 0; e < 4; e++) sacc[nt][e] = 0.f;

        #pragma unroll
        for (int ks = 0; ks < 8; ++ks) {
            #pragma unroll
            for (int np = 0; np < 4; np++) {
                int row = np*16 + (lane & 15);
                int ch = ks*2 + (lane >> 4);
                uint32_t q[4];
                ldsm4(q, sK + (uint32_t)row*256 +
                          ((uint32_t)((ch & 8) | ((ch ^ (row & 7)) & 7)) << 4));
                uint32_t bf0[2] = {q[0], q[2]}, bf1[2] = {q[1], q[3]};
                mma16(sacc[2*np],   qf[ks], bf0);
                mma16(sacc[2*np+1], qf[ks], bf1);
            }
        }

        // exp2 + pack P; causal mask only on the diagonal ktile
        const int qg0 = qt*64 + wrow + gid;
        const int kb  = kt*64;
        uint32_t pf[4][4];
        auto do_exp = [&](bool masked) {
            #pragma unroll
            for (int k2 = 0; k2 < 4; ++k2) {
                float p[2][4];
                #pragma unroll
                for (int j = 0; j < 2; j++) {
                    int nt = 2*k2 + j;
                    int c0 = kb + nt*8 + 2*tig;
                    if (masked) {
                        p[j][0] = (c0     <= qg0    ) ? exp2f(sacc[nt][0]) : 0.f;
                        p[j][1] = (c0 + 1 <= qg0    ) ? exp2f(sacc[nt][1]) : 0.f;
                        p[j][2] = (c0     <= qg0 + 8) ? exp2f(sacc[nt][2]) : 0.f;
                        p[j][3] = (c0 + 1 <= qg0 + 8) ? exp2f(sacc[nt][3]) : 0.f;
                    } else {
                        p[j][0] = exp2f(sacc[nt][0]);
                        p[j][1] = exp2f(sacc[nt][1]);
                        p[j][2] = exp2f(sacc[nt][2]);
                        p[j][3] = exp2f(sacc[nt][3]);
                    }
                }
                pf[k2][0] = f2h2(p[0][0], p[0][1]);
                pf[k2][1] = f2h2(p[0][2], p[0][3]);
                pf[k2][2] = f2h2(p[1][0], p[1][1]);
                pf[k2][3] = f2h2(p[1][2], p[1][3]);
                float2 t;
                t = __half22float2(*(__half2*)&pf[k2][0]); l0 += t.x + t.y;
                t = __half22float2(*(__half2*)&pf[k2][2]); l0 += t.x + t.y;
                t = __half22float2(*(__half2*)&pf[k2][1]); l1 += t.x + t.y;
                t = __half22float2(*(__half2*)&pf[k2][3]); l1 += t.x + t.y;
            }
        };
        if (kt == qt) do_exp(true); else do_exp(false);

        // O += P @ V : warp 16x128, k=64
        #pragma unroll
        for (int k2 = 0; k2 < 4; ++k2) {
            #pragma unroll
            for (int nb = 0; nb < 8; nb++) {
                int kr = k2*16 + (lane & 15);
                int ch = nb*2 + (lane >> 4);
                uint32_t q[4];
                ldsm4t(q, sV + (uint32_t)kr*256 +
                          ((uint32_t)((ch & 8) | ((ch ^ (kr & 7)) & 7)) << 4));
                uint32_t bf0[2] = {q[0], q[1]}, bf1[2] = {q[2], q[3]};
                mma16(oacc[2*nb],   pf[k2], bf0);
                mma16(oacc[2*nb+1], pf[k2], bf1);
            }
        }
    }

    l0 += __shfl_xor_sync(0xffffffff, l0, 1);
    l0 += __shfl_xor_sync(0xffffffff, l0, 2);
    l1 += __shfl_xor_sync(0xffffffff, l1, 1);
    l1 += __shfl_xor_sync(0xffffffff, l1, 2);
    const float inv0 = 1.f / l0, inv1 = 1.f / l1;

    const int r0 = q0 + wrow + gid;
    #pragma unroll
    for (int nt = 0; nt < 16; nt++) {
        int col = h*HD + nt*8 + 2*tig;
        *(uint32_t*)(AOh + (size_t)r0 * DMODEL + col) =
            f2h2(oacc[nt][0]*inv0, oacc[nt][1]*inv0);
        *(uint32_t*)(AOh + (size_t)(r0 + 8) * DMODEL + col) =
            f2h2(oacc[nt][2]*inv1, oacc[nt][3]*inv1);
    }
}

// ---------------- launch -----------------------------------------------------
extern "C" void kernel_launch(void* const* d_in, const int* in_sizes, int n_in,
                              void* d_out, int out_size)
{
    const float* x  = (const float*)d_in[0];
    const float* Wq = (const float*)d_in[1];
    const float* Wk = (const float*)d_in[2];
    const float* Wv = (const float*)d_in[3];
    const float* Wo = (const float*)d_in[4];
    float* out = (float*)d_out;

    __half *xh, *Wqh, *Wkh, *Wvh, *Woh, *Qh, *Kh, *Vh, *AOh;
    cudaGetSymbolAddress((void**)&xh,  g_xh);
    cudaGetSymbolAddress((void**)&Wqh, g_Wqh);
    cudaGetSymbolAddress((void**)&Wkh, g_Wkh);
    cudaGetSymbolAddress((void**)&Wvh, g_Wvh);
    cudaGetSymbolAddress((void**)&Woh, g_Woh);
    cudaGetSymbolAddress((void**)&Qh,  g_Qh);
    cudaGetSymbolAddress((void**)&Kh,  g_Kh);
    cudaGetSymbolAddress((void**)&Vh,  g_Vh);
    cudaGetSymbolAddress((void**)&AOh, g_AOh);

    cudaFuncSetAttribute(hgemm,    cudaFuncAttributeMaxDynamicSharedMemorySize, GEMM_SMEM);
    cudaFuncSetAttribute(flash_h2, cudaFuncAttributeMaxDynamicSharedMemorySize, FLASH_SMEM);

    rope_table_kernel<<<(T_SEQ*64 + 255)/256, 256>>>();
    conv_all<<<(int)((CONV_TOTAL + 1023)/1024), 256>>>(x, Wq, Wk, Wv, Wo);

    // fused QKV projection (fp16 out): tiles 0-15 -> Q, 16-19 -> K, 20-23 -> V
    hgemm<<<dim3(24, M_ROWS/128), 256, GEMM_SMEM>>>(
        xh, Wqh, Wkh, Wvh, Qh, Kh, Vh, 16, 4, DMODEL, 1);

    // in-place RoPE on Q and K in one launch; Q pre-scaled by FA_SCALE*log2(e)
    rope_qk_kernel<<<(NQ_ROPE + NK_ROPE + 255)/256, 256>>>(Qh, Kh, FA_SCALE*LOG2E);

    flash_h2<<<dim3(32, HQ, BATCH), 128, FLASH_SMEM>>>(Qh, Kh, Vh, AOh);

    // output projection (fp32 out)
    hgemm<<<dim3(16, M_ROWS/128), 256, GEMM_SMEM>>>(
        AOh, Woh, Woh, Woh, out, out, out, 16, 0, DMODEL, 0);
}

// round 11
// speedup vs baseline: 1.1941x; 1.0010x over previous
#include <cuda_runtime.h>
#include <cuda_fp16.h>
#include <math.h>
#include <stdint.h>

#define T_SEQ 2048
#define BATCH 2
#define DMODEL 2048
#define HQ 16
#define HKV 4
#define HD 128
#define M_ROWS (BATCH*T_SEQ)   /* 4096 */
#define DKV (HKV*HD)           /* 512 */
#define FA_SCALE 0.08838834764831845f
#define LOG2E 1.4426950408889634f

// ---------------- scratch ---------------------------------------------------
__device__ __half g_xh[M_ROWS*DMODEL];
__device__ __half g_Wqh[DMODEL*DMODEL];
__device__ __half g_Wkh[DMODEL*DKV];
__device__ __half g_Wvh[DMODEL*DKV];
__device__ __half g_Woh[DMODEL*DMODEL];
__device__ __half g_Qh[M_ROWS*DMODEL];
__device__ __half g_Kh[M_ROWS*DKV];
__device__ __half g_Vh[M_ROWS*DKV];
__device__ __half g_AOh[M_ROWS*DMODEL];
__device__ float  g_cos[T_SEQ*64];
__device__ float  g_sin[T_SEQ*64];

// ---------------- helpers ----------------------------------------------------
__device__ __forceinline__ uint32_t f2h2(float a, float b) {
    __half2 h = __halves2half2(__float2half_rn(a), __float2half_rn(b));
    return *reinterpret_cast<uint32_t*>(&h);
}
__device__ __forceinline__ uint32_t cvta_smem(const void* p) {
    uint32_t a;
    asm("{ .reg .u64 t; cvta.to.shared.u64 t, %1; cvt.u32.u64 %0, t; }"
        : "=r"(a) : "l"(p));
    return a;
}
__device__ __forceinline__ void mma16(float* d, const uint32_t* a, const uint32_t* b) {
    asm volatile("mma.sync.aligned.m16n8k16.row.col.f32.f16.f16.f32 "
        "{%0,%1,%2,%3}, {%4,%5,%6,%7}, {%8,%9}, {%0,%1,%2,%3};"
        : "+f"(d[0]), "+f"(d[1]), "+f"(d[2]), "+f"(d[3])
        : "r"(a[0]), "r"(a[1]), "r"(a[2]), "r"(a[3]), "r"(b[0]), "r"(b[1]));
}
__device__ __forceinline__ void ldsm4(uint32_t* r, uint32_t a) {
    asm volatile("ldmatrix.sync.aligned.m8n8.x4.shared.b16 {%0,%1,%2,%3}, [%4];"
        : "=r"(r[0]), "=r"(r[1]), "=r"(r[2]), "=r"(r[3]) : "r"(a));
}
__device__ __forceinline__ void ldsm4t(uint32_t* r, uint32_t a) {
    asm volatile("ldmatrix.sync.aligned.m8n8.x4.trans.shared.b16 {%0,%1,%2,%3}, [%4];"
        : "=r"(r[0]), "=r"(r[1]), "=r"(r[2]), "=r"(r[3]) : "r"(a));
}
__device__ __forceinline__ void cp16(uint32_t dst, const void* src) {
    asm volatile("cp.async.cg.shared.global [%0], [%1], 16;" :: "r"(dst), "l"(src));
}
#define CPCOMMIT() asm volatile("cp.async.commit_group;" ::: "memory")
#define CPWAIT1()  asm volatile("cp.async.wait_group 1;" ::: "memory")
#define CPWAIT0()  asm volatile("cp.async.wait_group 0;" ::: "memory")

// ---------------- input conversion fp32 -> fp16 (4 float4 per thread) -------
#define N_X  ((long)M_ROWS*DMODEL/4)
#define N_WQ ((long)DMODEL*DMODEL/4)
#define N_WK ((long)DMODEL*DKV/4)
#define CONV_TOTAL (N_X + 2*N_WQ + 2*N_WK)

__global__ void conv_all(const float* __restrict__ x, const float* __restrict__ wq,
                         const float* __restrict__ wk, const float* __restrict__ wv,
                         const float* __restrict__ wo) {
    long base = (long)blockIdx.x*1024 + threadIdx.x;
    #pragma unroll
    for (int u = 0; u < 4; u++) {
        long i = base + u*256;
        const float* src; __half* dst; long off;
        if (i < N_X)                       { src = x;  dst = g_xh;  off = i; }
        else if (i < N_X + N_WQ)           { src = wq; dst = g_Wqh; off = i - N_X; }
        else if (i < N_X + N_WQ + N_WK)    { src = wk; dst = g_Wkh; off = i - N_X - N_WQ; }
        else if (i < N_X + N_WQ + 2*N_WK)  { src = wv; dst = g_Wvh; off = i - N_X - N_WQ - N_WK; }
        else if (i < CONV_TOTAL)           { src = wo; dst = g_Woh; off = i - N_X - N_WQ - 2*N_WK; }
        else continue;
        float4 v = *(const float4*)(src + off*4);
        uint2 uu; uu.x = f2h2(v.x, v.y); uu.y = f2h2(v.z, v.w);
        *(uint2*)(dst + off*4) = uu;
    }
}

// ---------------- RoPE ------------------------------------------------------
// fp32 sincosf: matches the reference's own fp32 cos/sin of the fp32 angle,
// and avoids the serial FP64-trig bottleneck at the head of the graph.
__global__ void rope_table_kernel() {
    int idx = blockIdx.x*blockDim.x + threadIdx.x;
    if (idx >= T_SEQ*64) return;
    int t = idx >> 6, i = idx & 63;
    float inv = powf(10000.0f, -(float)i / 64.0f);
    float ang = (float)t * inv;
    float s, c;
    sincosf(ang, &s, &c);
    g_cos[idx] = c;
    g_sin[idx] = s;
}

// in-place fp16 RoPE on BOTH Q and K in one launch
#define NQ_ROPE (M_ROWS*HQ*32)
#define NK_ROPE (M_ROWS*HKV*32)
__global__ void rope_qk_kernel(__half* __restrict__ Qh, __half* __restrict__ Kh,
                               float qscale) {
    int idx = blockIdx.x*blockDim.x + threadIdx.x;
    __half* buf; int heads; float scale;
    if (idx < NQ_ROPE)                  { buf = Qh; heads = HQ;  scale = qscale; }
    else if (idx < NQ_ROPE + NK_ROPE)   { buf = Kh; heads = HKV; scale = 1.0f; idx -= NQ_ROPE; }
    else return;
    int i2 = idx & 31;
    int h = (idx >> 5) % heads;
    int m = idx / (32 * heads);
    int t = m & (T_SEQ - 1);
    int d0 = 2*i2;
    uint32_t* p = (uint32_t*)(buf + (size_t)m * heads * HD + h * HD);
    float2 a = __half22float2(*(__half2*)&p[i2]);
    float2 b = __half22float2(*(__half2*)&p[32 + i2]);
    float c0 = g_cos[t*64 + d0], c1 = g_cos[t*64 + d0 + 1];
    float s0 = g_sin[t*64 + d0], s1 = g_sin[t*64 + d0 + 1];
    p[i2]      = f2h2((a.x*c0 - b.x*s0)*scale, (a.y*c1 - b.y*s1)*scale);
    p[32 + i2] = f2h2((b.x*c0 + a.x*s0)*scale, (b.y*c1 + a.y*s1)*scale);
}

// ---------------- fp16 GEMM: cp.async 3-stage + ldmatrix, MTILE templated ----
// C[M,N] = A[M,K](fp16) @ B[K,N](fp16). MTILE = MT*64 rows, 128 cols, 8 warps
// (4 row-groups x 2 col-groups, warp tile (MT*16) x 64), BK=64.
#define GASZ(MT)  (64*(MT)*128)            /* A stage bytes */
#define GSTG(MT)  (GASZ(MT) + 16384)       /* stage bytes   */
#define GEMM_SMEM(MT) (3*GSTG(MT))

template<int MT>
__global__ __launch_bounds__(256) void hgemm(
    const __half* __restrict__ A,
    const __half* __restrict__ B0, const __half* __restrict__ B1, const __half* __restrict__ B2,
    void* __restrict__ C0, void* __restrict__ C1, void* __restrict__ C2,
    int t0, int t1, int K, int half_out)
{
    extern __shared__ char gsm[];
    const uint32_t sb = cvta_smem(gsm);

    const int tx = blockIdx.x;
    const __half* B; void* C; int N, cb;
    if (tx < t0)           { B = B0; C = C0; N = t0*128; cb = tx*128; }
    else if (tx < t0 + t1) { B = B1; C = C1; N = t1*128; cb = (tx - t0)*128; }
    else { B = B2; C = C2; N = ((int)gridDim.x - t0 - t1)*128; cb = (tx - t0 - t1)*128; }

    const int tid = threadIdx.x;
    const int lane = tid & 31, wid = tid >> 5;
    const int gid = lane >> 2, tig = lane & 3;
    const int wm = wid & 3, wn = wid >> 2;
    const int bm = blockIdx.y * (64*MT);
    const int nc = K >> 6;

    const int ar = tid >> 3, ac = tid & 7;
    const int bk = tid >> 4, bc = tid & 15;
    const uint32_t aswz = (uint32_t)(ac ^ (ar & 7)) << 4;
    const uint32_t bswz = (uint32_t)((bc & 8) | ((bc ^ (bk & 7)) & 7)) << 4;

    auto issue = [&](int c) {
        const uint32_t sA = sb + (c % 3)*GSTG(MT);
        const uint32_t sB = sA + GASZ(MT);
        const __half* Ag = A + (size_t)(bm + ar)*K + c*64 + ac*8;
        #pragma unroll
        for (int i = 0; i < 2*MT; i++)
            cp16(sA + (uint32_t)(ar + 32*i)*128 + aswz, Ag + (size_t)(32*i)*K);
        const __half* Bg = B + (size_t)(c*64 + bk)*N + cb + bc*8;
        #pragma unroll
        for (int i = 0; i < 4; i++)
            cp16(sB + (uint32_t)(bk + 16*i)*256 + bswz, Bg + (size_t)(16*i)*N);
        CPCOMMIT();
    };

    float acc[MT][8][4];
    #pragma unroll
    for (int mt = 0; mt < MT; mt++)
        #pragma unroll
        for (int nt = 0; nt < 8; nt++)
            #pragma unroll
            for (int e = 0; e < 4; e++) acc[mt][nt][e] = 0.f;

    issue(0); issue(1);

    for (int c = 0; c < nc; ++c) {
        if (c + 2 < nc) { CPWAIT1(); } else { CPWAIT0(); }
        __syncthreads();
        if (c + 2 < nc) issue(c + 2);

        const uint32_t sA = sb + (c % 3)*GSTG(MT);
        const uint32_t sB = sA + GASZ(MT);

        #pragma unroll
        for (int ks = 0; ks < 4; ++ks) {
            uint32_t af[MT][4];
            #pragma unroll
            for (int mt = 0; mt < MT; mt++) {
                int row = wm*(16*MT) + mt*16 + (lane & 15);
                int ch = ks*2 + (lane >> 4);
                ldsm4(af[mt], sA + (uint32_t)row*128 + ((uint32_t)(ch ^ (row & 7)) << 4));
            }
            uint32_t bf[8][2];
            #pragma unroll
            for (int nb = 0; nb < 4; nb++) {
                int kr = ks*16 + (lane & 15);
                int ch = wn*8 + nb*2 + (lane >> 4);
                uint32_t q[4];
                ldsm4t(q, sB + (uint32_t)kr*256 +
                          ((uint32_t)((ch & 8) | ((ch ^ (kr & 7)) & 7)) << 4));
                bf[2*nb][0] = q[0]; bf[2*nb][1] = q[1];
                bf[2*nb+1][0] = q[2]; bf[2*nb+1][1] = q[3];
            }
            #pragma unroll
            for (int mt = 0; mt < MT; mt++)
                #pragma unroll
                for (int nt = 0; nt < 8; nt++)
                    mma16(acc[mt][nt], af[mt], bf[nt]);
        }
    }

    if (half_out) {
        __half* Ch = (__half*)C;
        #pragma unroll
        for (int mt = 0; mt < MT; mt++) {
            int r0 = bm + wm*(16*MT) + mt*16 + gid;
            #pragma unroll
            for (int nt = 0; nt < 8; nt++) {
                int col = cb + wn*64 + nt*8 + 2*tig;
                *(uint32_t*)(Ch + (size_t)r0 * N + col)       = f2h2(acc[mt][nt][0], acc[mt][nt][1]);
                *(uint32_t*)(Ch + (size_t)(r0 + 8) * N + col) = f2h2(acc[mt][nt][2], acc[mt][nt][3]);
            }
        }
    } else {
        float* Cf = (float*)C;
        #pragma unroll
        for (int mt = 0; mt < MT; mt++) {
            int r0 = bm + wm*(16*MT) + mt*16 + gid;
            #pragma unroll
            for (int nt = 0; nt < 8; nt++) {
                int col = cb + wn*64 + nt*8 + 2*tig;
                *(float2*)(Cf + (size_t)r0 * N + col)       = make_float2(acc[mt][nt][0], acc[mt][nt][1]);
                *(float2*)(Cf + (size_t)(r0 + 8) * N + col) = make_float2(acc[mt][nt][2], acc[mt][nt][3]);
            }
        }
    }
}

// ---------------- flash attention: BQ=64, 4 warps, 2 CTAs/SM ----------------
#define FKVSTB 32768
#define FQSZ   16384
#define FLASH_SMEM (FQSZ + 3*FKVSTB)

__global__ __launch_bounds__(128) void flash_h2(
    const __half* __restrict__ Qh, const __half* __restrict__ Kh,
    const __half* __restrict__ Vh, __half* __restrict__ AOh)
{
    extern __shared__ char fsm[];
    const uint32_t sb = cvta_smem(fsm);
    const int tid = threadIdx.x, lane = tid & 31, wid = tid >> 5;
    const int gid = lane >> 2, tig = lane & 3;
    const int qt = 31 - blockIdx.x;          // big tiles first
    const int h = blockIdx.y, b = blockIdx.z;
    const int hk = h >> 2;
    const int wrow = wid * 16;
    const int q0 = b*T_SEQ + qt*64;
    const int nkt = qt + 1;

    uint32_t kvo[8]; uint32_t go[8];
    #pragma unroll
    for (int i = 0; i < 8; i++) {
        int id = tid + 128*i;
        int r = id >> 4, c = id & 15;
        kvo[i] = (uint32_t)r*256 + ((uint32_t)((c & 8) | ((c ^ (r & 7)) & 7)) << 4);
        go[i]  = (uint32_t)(r*DKV + c*8);
    }

    const __half* Kbase = Kh + (size_t)(b*T_SEQ)*DKV + hk*HD;
    const __half* Vbase = Vh + (size_t)(b*T_SEQ)*DKV + hk*HD;

    auto issue_kv = [&](int kt) {
        const uint32_t sK = sb + FQSZ + (kt % 3)*FKVSTB;
        const uint32_t sV = sK + 16384;
        const __half* Kg = Kbase + (size_t)(kt*64)*DKV;
        const __half* Vg = Vbase + (size_t)(kt*64)*DKV;
        #pragma unroll
        for (int i = 0; i < 8; i++) {
            cp16(sK + kvo[i], Kg + go[i]);
            cp16(sV + kvo[i], Vg + go[i]);
        }
        CPCOMMIT();
    };

    {
        const __half* Qg = Qh + (size_t)q0*DMODEL + h*HD;
        #pragma unroll
        for (int i = 0; i < 8; i++) {
            int id = tid + 128*i;
            int r = id >> 4;
            cp16(sb + kvo[i], Qg + (size_t)r*DMODEL + (id & 15)*8);
        }
        const uint32_t sK = sb + FQSZ, sV = sK + 16384;
        #pragma unroll
        for (int i = 0; i < 8; i++) {
            cp16(sK + kvo[i], Kbase + go[i]);
            cp16(sV + kvo[i], Vbase + go[i]);
        }
        CPCOMMIT();
        issue_kv(1);
    }

    float oacc[16][4];
    #pragma unroll
    for (int nt = 0; nt < 16; nt++)
        #pragma unroll
        for (int e = 0; e < 4; e++) oacc[nt][e] = 0.f;
    float l0 = 0.f, l1 = 0.f;

    uint32_t qf[8][4];
    bool qloaded = false;

    for (int kt = 0; kt < nkt; ++kt) {
        if (kt + 2 < nkt) { CPWAIT1(); } else { CPWAIT0(); }
        __syncthreads();
        if (kt + 2 < nkt) issue_kv(kt + 2);

        if (!qloaded) {
            #pragma unroll
            for (int ks = 0; ks < 8; ++ks) {
                int row = wrow + (lane & 15);
                int ch = ks*2 + (lane >> 4);
                ldsm4(qf[ks], sb + (uint32_t)row*256 +
                          ((uint32_t)((ch & 8) | ((ch ^ (row & 7)) & 7)) << 4));
            }
            qloaded = true;
        }

        const uint32_t sK = sb + FQSZ + (kt % 3)*FKVSTB;
        const uint32_t sV = sK + 16384;

        float sacc[8][4];
        #pragma unroll
        for (int nt = 0; nt < 8; nt++)
            #pragma unroll
            for (int e = 0; e < 4; e++) sacc[nt][e] = 0.f;

        #pragma unroll
        for (int ks = 0; ks < 8; ++ks) {
            #pragma unroll
            for (int np = 0; np < 4; np++) {
                int row = np*16 + (lane & 15);
                int ch = ks*2 + (lane >> 4);
                uint32_t q[4];
                ldsm4(q, sK + (uint32_t)row*256 +
                          ((uint32_t)((ch & 8) | ((ch ^ (row & 7)) & 7)) << 4));
                uint32_t bf0[2] = {q[0], q[2]}, bf1[2] = {q[1], q[3]};
                mma16(sacc[2*np],   qf[ks], bf0);
                mma16(sacc[2*np+1], qf[ks], bf1);
            }
        }

        const int qg0 = qt*64 + wrow + gid;
        const int kb  = kt*64;
        uint32_t pf[4][4];
        auto do_exp = [&](bool masked) {
            #pragma unroll
            for (int k2 = 0; k2 < 4; ++k2) {
                float p[2][4];
                #pragma unroll
                for (int j = 0; j < 2; j++) {
                    int nt = 2*k2 + j;
                    int c0 = kb + nt*8 + 2*tig;
                    if (masked) {
                        p[j][0] = (c0     <= qg0    ) ? exp2f(sacc[nt][0]) : 0.f;
                        p[j][1] = (c0 + 1 <= qg0    ) ? exp2f(sacc[nt][1]) : 0.f;
                        p[j][2] = (c0     <= qg0 + 8) ? exp2f(sacc[nt][2]) : 0.f;
                        p[j][3] = (c0 + 1 <= qg0 + 8) ? exp2f(sacc[nt][3]) : 0.f;
                    } else {
                        p[j][0] = exp2f(sacc[nt][0]);
                        p[j][1] = exp2f(sacc[nt][1]);
                        p[j][2] = exp2f(sacc[nt][2]);
                        p[j][3] = exp2f(sacc[nt][3]);
                    }
                }
                pf[k2][0] = f2h2(p[0][0], p[0][1]);
                pf[k2][1] = f2h2(p[0][2], p[0][3]);
                pf[k2][2] = f2h2(p[1][0], p[1][1]);
                pf[k2][3] = f2h2(p[1][2], p[1][3]);
                float2 t;
                t = __half22float2(*(__half2*)&pf[k2][0]); l0 += t.x + t.y;
                t = __half22float2(*(__half2*)&pf[k2][2]); l0 += t.x + t.y;
                t = __half22float2(*(__half2*)&pf[k2][1]); l1 += t.x + t.y;
                t = __half22float2(*(__half2*)&pf[k2][3]); l1 += t.x + t.y;
            }
        };
        if (kt == qt) do_exp(true); else do_exp(false);

        #pragma unroll
        for (int k2 = 0; k2 < 4; ++k2) {
            #pragma unroll
            for (int nb = 0; nb < 8; nb++) {
                int kr = k2*16 + (lane & 15);
                int ch = nb*2 + (lane >> 4);
                uint32_t q[4];
                ldsm4t(q, sV + (uint32_t)kr*256 +
                          ((uint32_t)((ch & 8) | ((ch ^ (kr & 7)) & 7)) << 4));
                uint32_t bf0[2] = {q[0], q[1]}, bf1[2] = {q[2], q[3]};
                mma16(oacc[2*nb],   pf[k2], bf0);
                mma16(oacc[2*nb+1], pf[k2], bf1);
            }
        }
    }

    l0 += __shfl_xor_sync(0xffffffff, l0, 1);
    l0 += __shfl_xor_sync(0xffffffff, l0, 2);
    l1 += __shfl_xor_sync(0xffffffff, l1, 1);
    l1 += __shfl_xor_sync(0xffffffff, l1, 2);
    const float inv0 = 1.f / l0, inv1 = 1.f / l1;

    const int r0 = q0 + wrow + gid;
    #pragma unroll
    for (int nt = 0; nt < 16; nt++) {
        int col = h*HD + nt*8 + 2*tig;
        *(uint32_t*)(AOh + (size_t)r0 * DMODEL + col) =
            f2h2(oacc[nt][0]*inv0, oacc[nt][1]*inv0);
        *(uint32_t*)(AOh + (size_t)(r0 + 8) * DMODEL + col) =
            f2h2(oacc[nt][2]*inv1, oacc[nt][3]*inv1);
    }
}

// ---------------- launch -----------------------------------------------------
extern "C" void kernel_launch(void* const* d_in, const int* in_sizes, int n_in,
                              void* d_out, int out_size)
{
    const float* x  = (const float*)d_in[0];
    const float* Wq = (const float*)d_in[1];
    const float* Wk = (const float*)d_in[2];
    const float* Wv = (const float*)d_in[3];
    const float* Wo = (const float*)d_in[4];
    float* out = (float*)d_out;

    __half *xh, *Wqh, *Wkh, *Wvh, *Woh, *Qh, *Kh, *Vh, *AOh;
    cudaGetSymbolAddress((void**)&xh,  g_xh);
    cudaGetSymbolAddress((void**)&Wqh, g_Wqh);
    cudaGetSymbolAddress((void**)&Wkh, g_Wkh);
    cudaGetSymbolAddress((void**)&Wvh, g_Wvh);
    cudaGetSymbolAddress((void**)&Woh, g_Woh);
    cudaGetSymbolAddress((void**)&Qh,  g_Qh);
    cudaGetSymbolAddress((void**)&Kh,  g_Kh);
    cudaGetSymbolAddress((void**)&Vh,  g_Vh);
    cudaGetSymbolAddress((void**)&AOh, g_AOh);

    cudaFuncSetAttribute(hgemm<2>, cudaFuncAttributeMaxDynamicSharedMemorySize, GEMM_SMEM(2));
    cudaFuncSetAttribute(hgemm<1>, cudaFuncAttributeMaxDynamicSharedMemorySize, GEMM_SMEM(1));
    cudaFuncSetAttribute(flash_h2, cudaFuncAttributeMaxDynamicSharedMemorySize, FLASH_SMEM);

    rope_table_kernel<<<(T_SEQ*64 + 255)/256, 256>>>();
    conv_all<<<(int)((CONV_TOTAL + 1023)/1024), 256>>>(x, Wq, Wk, Wv, Wo);

    // fused QKV projection (fp16 out): tiles 0-15 -> Q, 16-19 -> K, 20-23 -> V
    hgemm<2><<<dim3(24, M_ROWS/128), 256, GEMM_SMEM(2)>>>(
        xh, Wqh, Wkh, Wvh, Qh, Kh, Vh, 16, 4, DMODEL, 1);

    // in-place RoPE on Q and K in one launch; Q pre-scaled by FA_SCALE*log2(e)
    rope_qk_kernel<<<(NQ_ROPE + NK_ROPE + 255)/256, 256>>>(Qh, Kh, FA_SCALE*LOG2E);

    flash_h2<<<dim3(32, HQ, BATCH), 128, FLASH_SMEM>>>(Qh, Kh, Vh, AOh);

    // output projection (fp32 out), 64-row tiles: 1024 CTAs -> 5.7% wave waste
    hgemm<1><<<dim3(16, M_ROWS/64), 256, GEMM_SMEM(1)>>>(
        AOh, Woh, Woh, Woh, out, out, out, 16, 0, DMODEL, 0);
}